// round 14
// baseline (speedup 1.0000x reference)
#include <cuda_runtime.h>
#include <cuda_bf16.h>
#include <cstdint>

// ---------------------------------------------------------------- constants
#define N_ANCH   8192
#define DIM      64
#define JSPLIT   8
#define STRIPS   64            // 8192 / 128
#define BM       128
#define BN       64
#define CHUNKS   16            // 1024 / 64 per split
#define KSTEPS   4             // K = 64 (bf16 hi only)
#define THREADS  256
#define ROWB     144           // 64*2 + 16 pad (conflict-free ldmatrix)
#define MARGIN_F 0.5f
#define RBLOCKS  64
#define NCLS     128
#define MCAP     184
#define KBIAS    1024.0f

// SMEM mine: A 18432 | B x3 9216 | sq x3
#define OFF_A     0
#define OFF_B     18432
#define BSTRIDE   9216
#define OFF_SQ    46080
#define SMEM_MINE 46848
// SMEM posloss: member ids 768 | transposed emb DIM*MCAP*4
#define SMEM_PL   48640

// ---------------------------------------------------------------- scratch
__device__ unsigned int g_ebf[N_ANCH * 32];   // bf16 hi pairs, 128B/row
__device__ float g_sqb[N_ANCH];               // ||x||^2 + KBIAS
__device__ int   g_ccnt[NCLS];                // zero-init; reset by loss winner
__device__ int   g_members[NCLS * MCAP];
__device__ int   g_posidx[N_ANCH];
__device__ float2 g_neg[JSPLIT * N_ANCH];     // per-split best diff-class (val, j)
__device__ float g_partial[RBLOCKS];
__device__ unsigned int g_count;              // loss ticket
__device__ unsigned int g_pos_done;           // pos completion counter

// ---------------------------------------------------------------- PTX helpers
__device__ __forceinline__ uint32_t smem_u32(const void* p) {
    uint32_t a;
    asm("{ .reg .u64 t; cvta.to.shared.u64 t, %1; cvt.u32.u64 %0, t; }"
        : "=r"(a) : "l"(p));
    return a;
}
#define CP16(d, s) \
    asm volatile("cp.async.cg.shared.global [%0], [%1], 16;" \
                 :: "r"(d), "l"(s) : "memory")
#define CP_COMMIT() asm volatile("cp.async.commit_group;" ::: "memory")
#define CP_WAIT1()  asm volatile("cp.async.wait_group 1;" ::: "memory")

#define LDSM_X4(R, addr) \
    asm volatile("ldmatrix.sync.aligned.m8n8.x4.shared.b16 {%0,%1,%2,%3}, [%4];" \
                 : "=r"((R)[0]), "=r"((R)[1]), "=r"((R)[2]), "=r"((R)[3]) \
                 : "r"(addr))

#define MMA16816(D, A, B0, B1) \
    asm volatile("mma.sync.aligned.m16n8k16.row.col.f32.bf16.bf16.f32 " \
                 "{%0,%1,%2,%3},{%4,%5,%6,%7},{%8,%9},{%0,%1,%2,%3};" \
                 : "+f"((D)[0]), "+f"((D)[1]), "+f"((D)[2]), "+f"((D)[3]) \
                 : "r"((A)[0]), "r"((A)[1]), "r"((A)[2]), "r"((A)[3]), \
                   "r"(B0), "r"(B1))

// ---------------------------------------------------------------- kernel 0: prep
__global__ void prep_kernel(const float* __restrict__ emb,
                            const int* __restrict__ tgt) {
    int idx = blockIdx.x * blockDim.x + threadIdx.x;
    int row = idx >> 3, sub = idx & 7;
    const float4* src = reinterpret_cast<const float4*>(emb);
    float4 v0 = src[row * 16 + sub * 2];
    float4 v1 = src[row * 16 + sub * 2 + 1];

    unsigned int h[4];
    h[0] = ((unsigned)__bfloat16_as_ushort(__float2bfloat16(v0.y)) << 16) |
            (unsigned)__bfloat16_as_ushort(__float2bfloat16(v0.x));
    h[1] = ((unsigned)__bfloat16_as_ushort(__float2bfloat16(v0.w)) << 16) |
            (unsigned)__bfloat16_as_ushort(__float2bfloat16(v0.z));
    h[2] = ((unsigned)__bfloat16_as_ushort(__float2bfloat16(v1.y)) << 16) |
            (unsigned)__bfloat16_as_ushort(__float2bfloat16(v1.x));
    h[3] = ((unsigned)__bfloat16_as_ushort(__float2bfloat16(v1.w)) << 16) |
            (unsigned)__bfloat16_as_ushort(__float2bfloat16(v1.z));
    reinterpret_cast<uint4*>(g_ebf)[row * 8 + sub] =
        make_uint4(h[0], h[1], h[2], h[3]);

    float s = v0.x * v0.x + v0.y * v0.y + v0.z * v0.z + v0.w * v0.w +
              v1.x * v1.x + v1.y * v1.y + v1.z * v1.z + v1.w * v1.w;
    s += __shfl_xor_sync(0xFFFFFFFFu, s, 1);
    s += __shfl_xor_sync(0xFFFFFFFFu, s, 2);
    s += __shfl_xor_sync(0xFFFFFFFFu, s, 4);
    if (sub == 0) {
        g_sqb[row] = s + KBIAS;
        int c = tgt[row];
        int slot = atomicAdd(&g_ccnt[c], 1);
        if (slot < MCAP) g_members[c * MCAP + slot] = row;
    }
}

// A tile: 128 rows x 128B. B tile: 64 rows x 128B.
__device__ __forceinline__ void fill_a(uint32_t dst_sb, int row0, int tid) {
    const char* src = reinterpret_cast<const char*>(g_ebf);
#pragma unroll
    for (int k = 0; k < 4; k++) {
        int idx = tid + k * THREADS;
        int r = idx >> 3, c8 = idx & 7;
        CP16(dst_sb + r * ROWB + c8 * 16,
             src + (size_t)(row0 + r) * 128 + c8 * 16);
    }
}
__device__ __forceinline__ void fill_b(uint32_t dst_sb, int row0, int tid) {
    const char* src = reinterpret_cast<const char*>(g_ebf);
#pragma unroll
    for (int k = 0; k < 2; k++) {
        int idx = tid + k * THREADS;
        int r = idx >> 3, c8 = idx & 7;
        CP16(dst_sb + r * ROWB + c8 * 16,
             src + (size_t)(row0 + r) * 128 + c8 * 16);
    }
}

// ---------------------------------------------------------------- kernel 1: mining (R10 core + filter writeback)
__global__ __launch_bounds__(THREADS, 2)
void mine_kernel(const int* __restrict__ tgt) {
    extern __shared__ char smem[];
    const uint32_t sb = smem_u32(smem);
    const int tid = threadIdx.x, wid = tid >> 5, lane = tid & 31;
    const int wm = wid >> 1, wn = wid & 1;       // 4 x 2 warp grid
    const int m_warp = wm * 32, n_warp = wn * 32;
    const int strip = blockIdx.x, split = blockIdx.y;
    const int i0 = strip * BM;
    const int j0 = split * (N_ANCH / JSPLIT);

    float* s_sq = reinterpret_cast<float*>(smem + OFF_SQ);

    fill_a(sb + OFF_A, i0, tid);
    fill_b(sb + OFF_B, j0, tid);
    if (tid < BN) s_sq[tid] = g_sqb[j0 + tid];
    CP_COMMIT();
    fill_b(sb + OFF_B + BSTRIDE, j0 + BN, tid);
    if (tid < BN) s_sq[64 + tid] = g_sqb[j0 + BN + tid];
    CP_COMMIT();

    const float INF_F = __int_as_float(0x7f800000);
    float gm1[4], gm2[4];
#pragma unroll
    for (int s = 0; s < 4; s++) { gm1[s] = INF_F; gm2[s] = INF_F; }

    const uint32_t lmoff = (uint32_t)(lane & 15) * ROWB + ((lane & 16) ? 16 : 0);
    const uint32_t aA = sb + OFF_A + m_warp * ROWB + lmoff;

    CP_WAIT1();
    __syncthreads();
    uint32_t Af[2][KSTEPS][4];
#pragma unroll
    for (int mt = 0; mt < 2; mt++)
#pragma unroll
        for (int s = 0; s < KSTEPS; s++)
            LDSM_X4(Af[mt][s], aA + mt * (16 * ROWB) + s * 32);

    for (int t = 0; t < CHUNKS; t++) {
        const int buf = t % 3;
        if (t > 0) { CP_WAIT1(); __syncthreads(); }

        const uint32_t aB = sb + OFF_B + buf * BSTRIDE + n_warp * ROWB + lmoff;
        const float* sqv = s_sq + buf * 64;

        float d[2][4][4];
#pragma unroll
        for (int mt = 0; mt < 2; mt++)
#pragma unroll
            for (int nt = 0; nt < 4; nt++)
#pragma unroll
                for (int e = 0; e < 4; e++) d[mt][nt][e] = 0.f;

#pragma unroll
        for (int s = 0; s < KSTEPS; s++) {
            uint32_t Bf[2][4];
#pragma unroll
            for (int np = 0; np < 2; np++)
                LDSM_X4(Bf[np], aB + np * (16 * ROWB) + s * 32);
#pragma unroll
            for (int mt = 0; mt < 2; mt++)
#pragma unroll
                for (int nt = 0; nt < 4; nt++) {
                    int np = nt >> 1, sel = nt & 1;
                    MMA16816(d[mt][nt], Af[mt][s], Bf[np][sel], Bf[np][2 + sel]);
                }
        }

        if (t + 2 < CHUNKS) {
            const int nb = (t + 2) % 3;
            fill_b(sb + OFF_B + nb * BSTRIDE, j0 + (t + 2) * BN, tid);
            if (tid < BN) s_sq[nb * 64 + tid] = g_sqb[j0 + (t + 2) * BN + tid];
            CP_COMMIT();
        }

        const int jb10 = t * BN;
#pragma unroll
        for (int nt = 0; nt < 4; nt++)
#pragma unroll
            for (int c = 0; c < 2; c++) {
                int jl6 = n_warp + nt * 8 + (lane & 3) * 2 + c;
                unsigned jfield = (unsigned)(jb10 + jl6);
                float sqb = sqv[jl6];
#pragma unroll
                for (int mt = 0; mt < 2; mt++)
#pragma unroll
                    for (int h = 0; h < 2; h++) {
                        int sl = mt * 2 + h;
                        float key = fmaf(-2.0f, d[mt][nt][h * 2 + c], sqb);
                        float pk = __uint_as_float(
                            (__float_as_uint(key) & 0xFFFFFC00u) | jfield);
                        float sw = fmaxf(gm1[sl], pk);
                        gm1[sl] = fminf(gm1[sl], pk);
                        gm2[sl] = fminf(gm2[sl], sw);
                    }
            }
    }

    // Quad reduce
#pragma unroll
    for (int off = 1; off <= 2; off <<= 1) {
#pragma unroll
        for (int s = 0; s < 4; s++) {
            float o1 = __shfl_xor_sync(0xFFFFFFFFu, gm1[s], off);
            float o2 = __shfl_xor_sync(0xFFFFFFFFu, gm2[s], off);
            float n1 = fminf(gm1[s], o1);
            float n2 = fminf(fmaxf(gm1[s], o1), fminf(gm2[s], o2));
            gm1[s] = n1; gm2[s] = n2;
        }
    }

    // Cross-warp combine + class filter + writeback
    float2* s_sel = reinterpret_cast<float2*>(smem + OFF_B);
    __syncthreads();
    if ((lane & 3) == 0) {
#pragma unroll
        for (int mt = 0; mt < 2; mt++)
#pragma unroll
            for (int h = 0; h < 2; h++) {
                int sl = mt * 2 + h;
                int row = m_warp + mt * 16 + (lane >> 2) + h * 8;
                s_sel[wn * 128 + row] = make_float2(gm1[sl], gm2[sl]);
            }
    }
    __syncthreads();
    if (tid < 128) {
        float2 a = s_sel[tid];
        float2 b = s_sel[128 + tid];
        float n1 = fminf(a.x, b.x);
        float n2 = fminf(fmaxf(a.x, b.x), fminf(a.y, b.y));
        const int i = i0 + tid;
        const int mytgt = tgt[i];
        int j1 = j0 + (int)(__float_as_uint(n1) & 1023u);
        int j2 = j0 + (int)(__float_as_uint(n2) & 1023u);
        float bv; int bj;
        if (tgt[j1] != mytgt)      { bv = n1; bj = j1; }
        else if (tgt[j2] != mytgt) { bv = n2; bj = j2; }
        else                       { bv = INF_F; bj = 0x7FFFFFFF; }
        g_neg[split * N_ANCH + i] = make_float2(bv, __int_as_float(bj));
    }
}

// ---------------------------------------------------------------- kernel 2: pos (first NCLS CTAs) + loss (next RBLOCKS CTAs)
__global__ __launch_bounds__(THREADS, 2)
void posloss_kernel(const float* __restrict__ emb, float* __restrict__ out) {
    extern __shared__ char smem[];
    const int tid = threadIdx.x, lane = tid & 31, wid = tid >> 5;
    const int bid = blockIdx.x;

    if (bid < NCLS) {
        // ---------------- pos: exact hard positive for one class ----------------
        int*   sm_j = reinterpret_cast<int*>(smem);           // 768 B
        float* sm_e = reinterpret_cast<float*>(smem + 768);   // DIM*MCAP floats
        const int c = bid;
        const int m = min(g_ccnt[c], MCAP);

        for (int k = tid; k < m; k += THREADS) sm_j[k] = g_members[c * MCAP + k];
        __syncthreads();
        const float4* emb4 = reinterpret_cast<const float4*>(emb);
        for (int idx = tid; idx < m * 16; idx += THREADS) {
            int mm = idx >> 4, q = idx & 15;
            float4 v = emb4[(size_t)sm_j[mm] * 16 + q];
            sm_e[(q * 4 + 0) * MCAP + mm] = v.x;
            sm_e[(q * 4 + 1) * MCAP + mm] = v.y;
            sm_e[(q * 4 + 2) * MCAP + mm] = v.z;
            sm_e[(q * 4 + 3) * MCAP + mm] = v.w;
        }
        __syncthreads();

        for (int a = wid; a < m; a += 8) {
            float bestv = -1.0f;
            int   bestj = 0x7FFFFFFF;
            for (int pass = 0; pass * 32 < m; pass++) {
                int jm = pass * 32 + lane;
                int jc = jm < m ? jm : m - 1;
                float acc = 0.f;
#pragma unroll
                for (int dd = 0; dd < DIM; dd++) {
                    float va = sm_e[dd * MCAP + a];
                    float vj = sm_e[dd * MCAP + jc];
                    float df = va - vj;
                    acc = fmaf(df, df, acc);
                }
                float v = (jm < m) ? acc : -2.0f;
                int   j = (jm < m) ? sm_j[jm] : 0x7FFFFFFF;
                if (v > bestv || (v == bestv && j < bestj)) { bestv = v; bestj = j; }
            }
#pragma unroll
            for (int off = 16; off > 0; off >>= 1) {
                float ov = __shfl_xor_sync(0xFFFFFFFFu, bestv, off);
                int   oj = __shfl_xor_sync(0xFFFFFFFFu, bestj, off);
                if (ov > bestv || (ov == bestv && oj < bestj)) {
                    bestv = ov; bestj = oj;
                }
            }
            if (lane == 0) g_posidx[sm_j[a]] = bestj;
        }
        __threadfence();          // publish g_posidx (every thread)
        __syncthreads();
        if (tid == 0) atomicAdd(&g_pos_done, 1u);
        return;
    }

    // ---------------- loss: 2 threads per anchor ----------------
    float* red = reinterpret_cast<float*>(smem);              // 128 floats
    const int ab = bid - NCLS;
    const int a  = tid >> 1, sub = tid & 1;
    const int i  = ab * 128 + a;
    const float INF_F = __int_as_float(0x7f800000);

    // neg scan first (independent of pos)
    float bv = INF_F; int bj = 0;
#pragma unroll
    for (int s = 0; s < JSPLIT; s++) {
        float2 cnd = g_neg[s * N_ANCH + i];
        int j = __float_as_int(cnd.y);
        if (cnd.x < bv || (cnd.x == bv && j < bj)) { bv = cnd.x; bj = j; }
    }
    const int n = min(bj, N_ANCH - 1);

    // wait for all pos CTAs (scheduled before us; guaranteed progress)
    if (tid == 0) {
        unsigned d;
        do {
            asm volatile("ld.global.acquire.gpu.u32 %0, [%1];"
                         : "=r"(d) : "l"(&g_pos_done));
            if (d < NCLS) __nanosleep(200);
        } while (d < NCLS);
    }
    __syncthreads();
    const int p = g_posidx[i];

    const float4* ei = reinterpret_cast<const float4*>(emb + (size_t)i * DIM) + sub * 8;
    const float4* ep = reinterpret_cast<const float4*>(emb + (size_t)p * DIM) + sub * 8;
    const float4* en = reinterpret_cast<const float4*>(emb + (size_t)n * DIM) + sub * 8;
    float ap = 0.f, an = 0.f;
#pragma unroll
    for (int k = 0; k < 8; k++) {
        float4 vi = ei[k], vp = ep[k], vn = en[k];
        float dx;
        dx = vi.x - vp.x; ap += dx * dx;
        dx = vi.y - vp.y; ap += dx * dx;
        dx = vi.z - vp.z; ap += dx * dx;
        dx = vi.w - vp.w; ap += dx * dx;
        dx = vi.x - vn.x; an += dx * dx;
        dx = vi.y - vn.y; an += dx * dx;
        dx = vi.z - vn.z; an += dx * dx;
        dx = vi.w - vn.w; an += dx * dx;
    }
    float v = ap - an;
    v += __shfl_xor_sync(0xFFFFFFFFu, v, 1);
    if (sub == 0) red[a] = fmaxf(v + MARGIN_F, 0.0f);
    __syncthreads();

#pragma unroll
    for (int off = 64; off > 0; off >>= 1) {
        if (tid < off) red[tid] += red[tid + off];
        __syncthreads();
    }
    if (tid == 0) {
        g_partial[ab] = red[0];
        __threadfence();
        unsigned int ticket = atomicAdd(&g_count, 1u);
        if (ticket == RBLOCKS - 1) {
            float t = 0.f;
#pragma unroll 8
            for (int k = 0; k < RBLOCKS; k++) t += g_partial[k];
            out[0] = t / (float)N_ANCH;
            // reset all counters for the next graph replay
            for (int k = 0; k < NCLS; k++) g_ccnt[k] = 0;
            g_pos_done = 0;
            g_count = 0;
        }
    }
}

// ----------------------------------------------------------------
extern "C" void kernel_launch(void* const* d_in, const int* in_sizes, int n_in,
                              void* d_out, int out_size) {
    const float* emb = (const float*)d_in[0];
    const int*   tgt = (const int*)d_in[1];
    float*       out = (float*)d_out;

    cudaFuncSetAttribute(mine_kernel, cudaFuncAttributeMaxDynamicSharedMemorySize,
                         SMEM_MINE);
    cudaFuncSetAttribute(posloss_kernel, cudaFuncAttributeMaxDynamicSharedMemorySize,
                         SMEM_PL);

    prep_kernel<<<(N_ANCH * 8) / 256, 256>>>(emb, tgt);
    dim3 grid(STRIPS, JSPLIT);
    mine_kernel<<<grid, THREADS, SMEM_MINE>>>(tgt);
    posloss_kernel<<<NCLS + RBLOCKS, THREADS, SMEM_PL>>>(emb, out);
}

// round 15
// speedup vs baseline: 1.0306x; 1.0306x over previous
#include <cuda_runtime.h>
#include <cuda_bf16.h>
#include <cstdint>

// ---------------------------------------------------------------- constants
#define N_ANCH   8192
#define DIM      64
#define JSPLIT   8
#define STRIPS   64            // 8192 / 128
#define BM       128
#define BN       64
#define CHUNKS   16            // 1024 / 64 per split
#define KSTEPS   4             // K = 64 (bf16 hi only)
#define THREADS  256
#define ROWB     144           // 64*2 + 16 pad (conflict-free ldmatrix)
#define MARGIN_F 0.5f
#define RBLOCKS  64
#define NCLS     128
#define MCAP     184
#define KBIAS    1024.0f

// SMEM mine: A 18432 | B x3 9216 | sq x3
#define OFF_A     0
#define OFF_B     18432
#define BSTRIDE   9216
#define OFF_SQ    46080
#define SMEM_MINE 46848
// SMEM pos: member ids 768 | transposed emb DIM*MCAP*4 = 47104
#define SMEM_POS  47872

// ---------------------------------------------------------------- scratch
__device__ unsigned int g_ebf[N_ANCH * 32];   // bf16 hi pairs, 128B/row
__device__ float g_sqb[N_ANCH];               // ||x||^2 + KBIAS
__device__ int   g_ccnt[NCLS];                // zero-init; reset by loss winner
__device__ int   g_members[NCLS * MCAP];
__device__ int   g_posidx[N_ANCH];
__device__ float2 g_neg[JSPLIT * N_ANCH];     // per-split best diff-class (val, j)
__device__ float g_partial[RBLOCKS];
__device__ unsigned int g_count;

// ---------------------------------------------------------------- PTX helpers
__device__ __forceinline__ uint32_t smem_u32(const void* p) {
    uint32_t a;
    asm("{ .reg .u64 t; cvta.to.shared.u64 t, %1; cvt.u32.u64 %0, t; }"
        : "=r"(a) : "l"(p));
    return a;
}
#define CP16(d, s) \
    asm volatile("cp.async.cg.shared.global [%0], [%1], 16;" \
                 :: "r"(d), "l"(s) : "memory")
#define CP_COMMIT() asm volatile("cp.async.commit_group;" ::: "memory")
#define CP_WAIT1()  asm volatile("cp.async.wait_group 1;" ::: "memory")

#define LDSM_X4(R, addr) \
    asm volatile("ldmatrix.sync.aligned.m8n8.x4.shared.b16 {%0,%1,%2,%3}, [%4];" \
                 : "=r"((R)[0]), "=r"((R)[1]), "=r"((R)[2]), "=r"((R)[3]) \
                 : "r"(addr))

#define MMA16816(D, A, B0, B1) \
    asm volatile("mma.sync.aligned.m16n8k16.row.col.f32.bf16.bf16.f32 " \
                 "{%0,%1,%2,%3},{%4,%5,%6,%7},{%8,%9},{%0,%1,%2,%3};" \
                 : "+f"((D)[0]), "+f"((D)[1]), "+f"((D)[2]), "+f"((D)[3]) \
                 : "r"((A)[0]), "r"((A)[1]), "r"((A)[2]), "r"((A)[3]), \
                   "r"(B0), "r"(B1))

// ---------------------------------------------------------------- kernel 0: prep
// 2 rows per thread (4 independent LDG.128 in flight), 8 threads per row.
__global__ void prep_kernel(const float* __restrict__ emb,
                            const int* __restrict__ tgt) {
    int idx = blockIdx.x * blockDim.x + threadIdx.x;   // 32768 threads
    int row0 = idx >> 3, sub = idx & 7;
    const float4* src = reinterpret_cast<const float4*>(emb);

#pragma unroll
    for (int rr = 0; rr < 2; rr++) {
        int row = row0 + rr * 4096;
        float4 v0 = src[row * 16 + sub * 2];
        float4 v1 = src[row * 16 + sub * 2 + 1];

        unsigned int h[4];
        h[0] = ((unsigned)__bfloat16_as_ushort(__float2bfloat16(v0.y)) << 16) |
                (unsigned)__bfloat16_as_ushort(__float2bfloat16(v0.x));
        h[1] = ((unsigned)__bfloat16_as_ushort(__float2bfloat16(v0.w)) << 16) |
                (unsigned)__bfloat16_as_ushort(__float2bfloat16(v0.z));
        h[2] = ((unsigned)__bfloat16_as_ushort(__float2bfloat16(v1.y)) << 16) |
                (unsigned)__bfloat16_as_ushort(__float2bfloat16(v1.x));
        h[3] = ((unsigned)__bfloat16_as_ushort(__float2bfloat16(v1.w)) << 16) |
                (unsigned)__bfloat16_as_ushort(__float2bfloat16(v1.z));
        reinterpret_cast<uint4*>(g_ebf)[row * 8 + sub] =
            make_uint4(h[0], h[1], h[2], h[3]);

        float s = v0.x * v0.x + v0.y * v0.y + v0.z * v0.z + v0.w * v0.w +
                  v1.x * v1.x + v1.y * v1.y + v1.z * v1.z + v1.w * v1.w;
        s += __shfl_xor_sync(0xFFFFFFFFu, s, 1);
        s += __shfl_xor_sync(0xFFFFFFFFu, s, 2);
        s += __shfl_xor_sync(0xFFFFFFFFu, s, 4);
        if (sub == 0) {
            g_sqb[row] = s + KBIAS;
            int c = tgt[row];
            int slot = atomicAdd(&g_ccnt[c], 1);
            if (slot < MCAP) g_members[c * MCAP + slot] = row;
        }
    }
}

// ---------------------------------------------------------------- kernel 1: exact positives (1 class per CTA)
__global__ __launch_bounds__(THREADS, 2)
void pos_kernel(const float* __restrict__ emb) {
    extern __shared__ char psmem[];
    int*   sm_j = reinterpret_cast<int*>(psmem);
    float* sm_e = reinterpret_cast<float*>(psmem + 768);
    const int tid = threadIdx.x, lane = tid & 31, wid = tid >> 5;
    const int c = blockIdx.x;
    const int m = min(g_ccnt[c], MCAP);

    for (int k = tid; k < m; k += THREADS) sm_j[k] = g_members[c * MCAP + k];
    __syncthreads();
    const float4* emb4 = reinterpret_cast<const float4*>(emb);
    for (int idx = tid; idx < m * 16; idx += THREADS) {
        int mm = idx >> 4, q = idx & 15;
        float4 v = emb4[(size_t)sm_j[mm] * 16 + q];
        sm_e[(q * 4 + 0) * MCAP + mm] = v.x;
        sm_e[(q * 4 + 1) * MCAP + mm] = v.y;
        sm_e[(q * 4 + 2) * MCAP + mm] = v.z;
        sm_e[(q * 4 + 3) * MCAP + mm] = v.w;
    }
    __syncthreads();

    for (int a = wid; a < m; a += 8) {
        float bestv = -1.0f;
        int   bestj = 0x7FFFFFFF;
        for (int pass = 0; pass * 32 < m; pass++) {
            int jm = pass * 32 + lane;
            int jc = jm < m ? jm : m - 1;
            float acc = 0.f;
#pragma unroll
            for (int dd = 0; dd < DIM; dd++) {
                float va = sm_e[dd * MCAP + a];
                float vj = sm_e[dd * MCAP + jc];
                float df = va - vj;
                acc = fmaf(df, df, acc);
            }
            float v = (jm < m) ? acc : -2.0f;
            int   j = (jm < m) ? sm_j[jm] : 0x7FFFFFFF;
            if (v > bestv || (v == bestv && j < bestj)) { bestv = v; bestj = j; }
        }
#pragma unroll
        for (int off = 16; off > 0; off >>= 1) {
            float ov = __shfl_xor_sync(0xFFFFFFFFu, bestv, off);
            int   oj = __shfl_xor_sync(0xFFFFFFFFu, bestj, off);
            if (ov > bestv || (ov == bestv && oj < bestj)) {
                bestv = ov; bestj = oj;
            }
        }
        if (lane == 0) g_posidx[sm_j[a]] = bestj;
    }
}

// A tile: 128 rows x 128B. B tile: 64 rows x 128B.
__device__ __forceinline__ void fill_a(uint32_t dst_sb, int row0, int tid) {
    const char* src = reinterpret_cast<const char*>(g_ebf);
#pragma unroll
    for (int k = 0; k < 4; k++) {
        int idx = tid + k * THREADS;
        int r = idx >> 3, c8 = idx & 7;
        CP16(dst_sb + r * ROWB + c8 * 16,
             src + (size_t)(row0 + r) * 128 + c8 * 16);
    }
}
__device__ __forceinline__ void fill_b(uint32_t dst_sb, int row0, int tid) {
    const char* src = reinterpret_cast<const char*>(g_ebf);
#pragma unroll
    for (int k = 0; k < 2; k++) {
        int idx = tid + k * THREADS;
        int r = idx >> 3, c8 = idx & 7;
        CP16(dst_sb + r * ROWB + c8 * 16,
             src + (size_t)(row0 + r) * 128 + c8 * 16);
    }
}

// ---------------------------------------------------------------- kernel 2: mining (R10 core + filter writeback)
__global__ __launch_bounds__(THREADS, 2)
void mine_kernel(const int* __restrict__ tgt) {
    extern __shared__ char smem[];
    const uint32_t sb = smem_u32(smem);
    const int tid = threadIdx.x, wid = tid >> 5, lane = tid & 31;
    const int wm = wid >> 1, wn = wid & 1;       // 4 x 2 warp grid
    const int m_warp = wm * 32, n_warp = wn * 32;
    const int strip = blockIdx.x, split = blockIdx.y;
    const int i0 = strip * BM;
    const int j0 = split * (N_ANCH / JSPLIT);

    float* s_sq = reinterpret_cast<float*>(smem + OFF_SQ);

    fill_a(sb + OFF_A, i0, tid);
    fill_b(sb + OFF_B, j0, tid);
    if (tid < BN) s_sq[tid] = g_sqb[j0 + tid];
    CP_COMMIT();
    fill_b(sb + OFF_B + BSTRIDE, j0 + BN, tid);
    if (tid < BN) s_sq[64 + tid] = g_sqb[j0 + BN + tid];
    CP_COMMIT();

    const float INF_F = __int_as_float(0x7f800000);
    float gm1[4], gm2[4];
#pragma unroll
    for (int s = 0; s < 4; s++) { gm1[s] = INF_F; gm2[s] = INF_F; }

    const uint32_t lmoff = (uint32_t)(lane & 15) * ROWB + ((lane & 16) ? 16 : 0);
    const uint32_t aA = sb + OFF_A + m_warp * ROWB + lmoff;

    CP_WAIT1();
    __syncthreads();
    uint32_t Af[2][KSTEPS][4];
#pragma unroll
    for (int mt = 0; mt < 2; mt++)
#pragma unroll
        for (int s = 0; s < KSTEPS; s++)
            LDSM_X4(Af[mt][s], aA + mt * (16 * ROWB) + s * 32);

    for (int t = 0; t < CHUNKS; t++) {
        const int buf = t % 3;
        if (t > 0) { CP_WAIT1(); __syncthreads(); }

        const uint32_t aB = sb + OFF_B + buf * BSTRIDE + n_warp * ROWB + lmoff;
        const float* sqv = s_sq + buf * 64;

        float d[2][4][4];
#pragma unroll
        for (int mt = 0; mt < 2; mt++)
#pragma unroll
            for (int nt = 0; nt < 4; nt++)
#pragma unroll
                for (int e = 0; e < 4; e++) d[mt][nt][e] = 0.f;

#pragma unroll
        for (int s = 0; s < KSTEPS; s++) {
            uint32_t Bf[2][4];
#pragma unroll
            for (int np = 0; np < 2; np++)
                LDSM_X4(Bf[np], aB + np * (16 * ROWB) + s * 32);
#pragma unroll
            for (int mt = 0; mt < 2; mt++)
#pragma unroll
                for (int nt = 0; nt < 4; nt++) {
                    int np = nt >> 1, sel = nt & 1;
                    MMA16816(d[mt][nt], Af[mt][s], Bf[np][sel], Bf[np][2 + sel]);
                }
        }

        if (t + 2 < CHUNKS) {
            const int nb = (t + 2) % 3;
            fill_b(sb + OFF_B + nb * BSTRIDE, j0 + (t + 2) * BN, tid);
            if (tid < BN) s_sq[nb * 64 + tid] = g_sqb[j0 + (t + 2) * BN + tid];
            CP_COMMIT();
        }

        const int jb10 = t * BN;
#pragma unroll
        for (int nt = 0; nt < 4; nt++)
#pragma unroll
            for (int c = 0; c < 2; c++) {
                int jl6 = n_warp + nt * 8 + (lane & 3) * 2 + c;
                unsigned jfield = (unsigned)(jb10 + jl6);
                float sqb = sqv[jl6];
#pragma unroll
                for (int mt = 0; mt < 2; mt++)
#pragma unroll
                    for (int h = 0; h < 2; h++) {
                        int sl = mt * 2 + h;
                        float key = fmaf(-2.0f, d[mt][nt][h * 2 + c], sqb);
                        float pk = __uint_as_float(
                            (__float_as_uint(key) & 0xFFFFFC00u) | jfield);
                        float sw = fmaxf(gm1[sl], pk);
                        gm1[sl] = fminf(gm1[sl], pk);
                        gm2[sl] = fminf(gm2[sl], sw);
                    }
            }
    }

    // Quad reduce
#pragma unroll
    for (int off = 1; off <= 2; off <<= 1) {
#pragma unroll
        for (int s = 0; s < 4; s++) {
            float o1 = __shfl_xor_sync(0xFFFFFFFFu, gm1[s], off);
            float o2 = __shfl_xor_sync(0xFFFFFFFFu, gm2[s], off);
            float n1 = fminf(gm1[s], o1);
            float n2 = fminf(fmaxf(gm1[s], o1), fminf(gm2[s], o2));
            gm1[s] = n1; gm2[s] = n2;
        }
    }

    // Cross-warp combine + class filter + writeback
    float2* s_sel = reinterpret_cast<float2*>(smem + OFF_B);
    __syncthreads();
    if ((lane & 3) == 0) {
#pragma unroll
        for (int mt = 0; mt < 2; mt++)
#pragma unroll
            for (int h = 0; h < 2; h++) {
                int sl = mt * 2 + h;
                int row = m_warp + mt * 16 + (lane >> 2) + h * 8;
                s_sel[wn * 128 + row] = make_float2(gm1[sl], gm2[sl]);
            }
    }
    __syncthreads();
    if (tid < 128) {
        float2 a = s_sel[tid];
        float2 b = s_sel[128 + tid];
        float n1 = fminf(a.x, b.x);
        float n2 = fminf(fmaxf(a.x, b.x), fminf(a.y, b.y));
        const int i = i0 + tid;
        const int mytgt = tgt[i];
        int j1 = j0 + (int)(__float_as_uint(n1) & 1023u);
        int j2 = j0 + (int)(__float_as_uint(n2) & 1023u);
        float bv; int bj;
        if (tgt[j1] != mytgt)      { bv = n1; bj = j1; }
        else if (tgt[j2] != mytgt) { bv = n2; bj = j2; }
        else                       { bv = INF_F; bj = 0x7FFFFFFF; }
        g_neg[split * N_ANCH + i] = make_float2(bv, __int_as_float(bj));
    }
}

// ---------------------------------------------------------------- kernel 3: loss + mean (2 threads/anchor)
__global__ void loss_kernel(const float* __restrict__ emb,
                            float* __restrict__ out) {
    __shared__ float red[128];
    const int tid = threadIdx.x;
    const int a = tid >> 1, sub = tid & 1;
    const int i = blockIdx.x * 128 + a;
    const float INF_F = __int_as_float(0x7f800000);

    float bv = INF_F; int bj = 0;
#pragma unroll
    for (int s = 0; s < JSPLIT; s++) {
        float2 cnd = g_neg[s * N_ANCH + i];
        int j = __float_as_int(cnd.y);
        if (cnd.x < bv || (cnd.x == bv && j < bj)) { bv = cnd.x; bj = j; }
    }
    const int n = min(bj, N_ANCH - 1);   // sentinel clamp (unreachable)
    const int p = g_posidx[i];

    const float4* ei = reinterpret_cast<const float4*>(emb + (size_t)i * DIM) + sub * 8;
    const float4* ep = reinterpret_cast<const float4*>(emb + (size_t)p * DIM) + sub * 8;
    const float4* en = reinterpret_cast<const float4*>(emb + (size_t)n * DIM) + sub * 8;
    float ap = 0.f, an = 0.f;
#pragma unroll
    for (int k = 0; k < 8; k++) {
        float4 vi = ei[k], vp = ep[k], vn = en[k];
        float dx;
        dx = vi.x - vp.x; ap += dx * dx;
        dx = vi.y - vp.y; ap += dx * dx;
        dx = vi.z - vp.z; ap += dx * dx;
        dx = vi.w - vp.w; ap += dx * dx;
        dx = vi.x - vn.x; an += dx * dx;
        dx = vi.y - vn.y; an += dx * dx;
        dx = vi.z - vn.z; an += dx * dx;
        dx = vi.w - vn.w; an += dx * dx;
    }
    float v = ap - an;
    v += __shfl_xor_sync(0xFFFFFFFFu, v, 1);
    if (sub == 0) red[a] = fmaxf(v + MARGIN_F, 0.0f);
    __syncthreads();

#pragma unroll
    for (int off = 64; off > 0; off >>= 1) {
        if (tid < off) red[tid] += red[tid + off];
        __syncthreads();
    }
    if (tid == 0) {
        g_partial[blockIdx.x] = red[0];
        __threadfence();
        unsigned int ticket = atomicAdd(&g_count, 1u);
        if (ticket == RBLOCKS - 1) {
            float t = 0.f;
#pragma unroll 8
            for (int k = 0; k < RBLOCKS; k++) t += g_partial[k];
            out[0] = t / (float)N_ANCH;
            // reset counters for the next graph replay
            for (int k = 0; k < NCLS; k++) g_ccnt[k] = 0;
            g_count = 0;
        }
    }
}

// ----------------------------------------------------------------
extern "C" void kernel_launch(void* const* d_in, const int* in_sizes, int n_in,
                              void* d_out, int out_size) {
    const float* emb = (const float*)d_in[0];
    const int*   tgt = (const int*)d_in[1];
    float*       out = (float*)d_out;

    cudaFuncSetAttribute(mine_kernel, cudaFuncAttributeMaxDynamicSharedMemorySize,
                         SMEM_MINE);
    cudaFuncSetAttribute(pos_kernel, cudaFuncAttributeMaxDynamicSharedMemorySize,
                         SMEM_POS);

    prep_kernel<<<(N_ANCH * 4) / 256, 256>>>(emb, tgt);
    pos_kernel<<<NCLS, THREADS, SMEM_POS>>>(emb);
    dim3 grid(STRIPS, JSPLIT);
    mine_kernel<<<grid, THREADS, SMEM_MINE>>>(tgt);
    loss_kernel<<<RBLOCKS, 256>>>(emb, out);
}

// round 16
// speedup vs baseline: 1.0891x; 1.0568x over previous
#include <cuda_runtime.h>
#include <cuda_bf16.h>
#include <cstdint>

// ---------------------------------------------------------------- constants
#define N_ANCH   8192
#define DIM      64
#define JSPLIT   8
#define STRIPS   64            // 8192 / 128
#define BM       128
#define BN       64
#define CHUNKS   16            // 1024 / 64 per split
#define KSTEPS   4             // K = 64 (bf16 hi only)
#define THREADS  256
#define ROWB     144           // 64*2 + 16 pad (conflict-free ldmatrix)
#define MARGIN_F 0.5f
#define RBLOCKS  128
#define NCLS     128
#define MCAP     184
#define KBIAS    1024.0f

// SMEM mine: A 18432 | B x3 9216 | sq x3
#define OFF_A     0
#define OFF_B     18432
#define BSTRIDE   9216
#define OFF_SQ    46080
#define SMEM_MINE 46848
// SMEM pos: member ids 768 | transposed emb DIM*MCAP*4 = 47104
#define SMEM_POS  47872

// ---------------------------------------------------------------- scratch
__device__ unsigned int g_ebf[N_ANCH * 32];   // bf16 hi pairs, 128B/row
__device__ float g_sqb[N_ANCH];               // ||x||^2 + KBIAS
__device__ int   g_ccnt[NCLS];                // zero-init; reset by loss winner
__device__ int   g_members[NCLS * MCAP];
__device__ int   g_posidx[N_ANCH];
__device__ float2 g_neg[JSPLIT * N_ANCH];     // per-split best diff-class (val, j)
__device__ float g_partial[RBLOCKS];
__device__ unsigned int g_count;

// ---------------------------------------------------------------- PTX helpers
__device__ __forceinline__ uint32_t smem_u32(const void* p) {
    uint32_t a;
    asm("{ .reg .u64 t; cvta.to.shared.u64 t, %1; cvt.u32.u64 %0, t; }"
        : "=r"(a) : "l"(p));
    return a;
}
#define CP16(d, s) \
    asm volatile("cp.async.cg.shared.global [%0], [%1], 16;" \
                 :: "r"(d), "l"(s) : "memory")
#define CP_COMMIT() asm volatile("cp.async.commit_group;" ::: "memory")
#define CP_WAIT1()  asm volatile("cp.async.wait_group 1;" ::: "memory")

#define LDSM_X4(R, addr) \
    asm volatile("ldmatrix.sync.aligned.m8n8.x4.shared.b16 {%0,%1,%2,%3}, [%4];" \
                 : "=r"((R)[0]), "=r"((R)[1]), "=r"((R)[2]), "=r"((R)[3]) \
                 : "r"(addr))

#define MMA16816(D, A, B0, B1) \
    asm volatile("mma.sync.aligned.m16n8k16.row.col.f32.bf16.bf16.f32 " \
                 "{%0,%1,%2,%3},{%4,%5,%6,%7},{%8,%9},{%0,%1,%2,%3};" \
                 : "+f"((D)[0]), "+f"((D)[1]), "+f"((D)[2]), "+f"((D)[3]) \
                 : "r"((A)[0]), "r"((A)[1]), "r"((A)[2]), "r"((A)[3]), \
                   "r"(B0), "r"(B1))

// ---------------------------------------------------------------- kernel 0: prep
__global__ void prep_kernel(const float* __restrict__ emb,
                            const int* __restrict__ tgt) {
    int idx = blockIdx.x * blockDim.x + threadIdx.x;   // 32768 threads
    int row0 = idx >> 3, sub = idx & 7;
    const float4* src = reinterpret_cast<const float4*>(emb);

#pragma unroll
    for (int rr = 0; rr < 2; rr++) {
        int row = row0 + rr * 4096;
        float4 v0 = src[row * 16 + sub * 2];
        float4 v1 = src[row * 16 + sub * 2 + 1];

        unsigned int h[4];
        h[0] = ((unsigned)__bfloat16_as_ushort(__float2bfloat16(v0.y)) << 16) |
                (unsigned)__bfloat16_as_ushort(__float2bfloat16(v0.x));
        h[1] = ((unsigned)__bfloat16_as_ushort(__float2bfloat16(v0.w)) << 16) |
                (unsigned)__bfloat16_as_ushort(__float2bfloat16(v0.z));
        h[2] = ((unsigned)__bfloat16_as_ushort(__float2bfloat16(v1.y)) << 16) |
                (unsigned)__bfloat16_as_ushort(__float2bfloat16(v1.x));
        h[3] = ((unsigned)__bfloat16_as_ushort(__float2bfloat16(v1.w)) << 16) |
                (unsigned)__bfloat16_as_ushort(__float2bfloat16(v1.z));
        reinterpret_cast<uint4*>(g_ebf)[row * 8 + sub] =
            make_uint4(h[0], h[1], h[2], h[3]);

        float s = v0.x * v0.x + v0.y * v0.y + v0.z * v0.z + v0.w * v0.w +
                  v1.x * v1.x + v1.y * v1.y + v1.z * v1.z + v1.w * v1.w;
        s += __shfl_xor_sync(0xFFFFFFFFu, s, 1);
        s += __shfl_xor_sync(0xFFFFFFFFu, s, 2);
        s += __shfl_xor_sync(0xFFFFFFFFu, s, 4);
        if (sub == 0) {
            g_sqb[row] = s + KBIAS;
            int c = tgt[row];
            int slot = atomicAdd(&g_ccnt[c], 1);
            if (slot < MCAP) g_members[c * MCAP + slot] = row;
        }
    }
}

// ---------------------------------------------------------------- kernel 1: exact positives (4 CTAs per class)
__global__ __launch_bounds__(THREADS, 2)
void pos_kernel(const float* __restrict__ emb) {
    extern __shared__ char psmem[];
    int*   sm_j = reinterpret_cast<int*>(psmem);
    float* sm_e = reinterpret_cast<float*>(psmem + 768);
    const int tid = threadIdx.x, lane = tid & 31, wid = tid >> 5;
    const int c = blockIdx.x >> 2;          // class
    const int q = blockIdx.x & 3;           // anchor quarter
    const int m = min(g_ccnt[c], MCAP);

    for (int k = tid; k < m; k += THREADS) sm_j[k] = g_members[c * MCAP + k];
    __syncthreads();
    const float4* emb4 = reinterpret_cast<const float4*>(emb);
    for (int idx = tid; idx < m * 16; idx += THREADS) {
        int mm = idx >> 4, qq = idx & 15;
        float4 v = emb4[(size_t)sm_j[mm] * 16 + qq];
        sm_e[(qq * 4 + 0) * MCAP + mm] = v.x;
        sm_e[(qq * 4 + 1) * MCAP + mm] = v.y;
        sm_e[(qq * 4 + 2) * MCAP + mm] = v.z;
        sm_e[(qq * 4 + 3) * MCAP + mm] = v.w;
    }
    __syncthreads();

    for (int a = q + 4 * wid; a < m; a += 32) {
        float bestv = -1.0f;
        int   bestj = 0x7FFFFFFF;
        for (int pass = 0; pass * 32 < m; pass++) {
            int jm = pass * 32 + lane;
            int jc = jm < m ? jm : m - 1;
            float acc0 = 0.f, acc1 = 0.f;       // split chain
#pragma unroll
            for (int dd = 0; dd < DIM; dd += 2) {
                float d0 = sm_e[dd * MCAP + a] - sm_e[dd * MCAP + jc];
                float d1 = sm_e[(dd + 1) * MCAP + a] - sm_e[(dd + 1) * MCAP + jc];
                acc0 = fmaf(d0, d0, acc0);
                acc1 = fmaf(d1, d1, acc1);
            }
            float acc = acc0 + acc1;
            float v = (jm < m) ? acc : -2.0f;
            int   j = (jm < m) ? sm_j[jm] : 0x7FFFFFFF;
            if (v > bestv || (v == bestv && j < bestj)) { bestv = v; bestj = j; }
        }
#pragma unroll
        for (int off = 16; off > 0; off >>= 1) {
            float ov = __shfl_xor_sync(0xFFFFFFFFu, bestv, off);
            int   oj = __shfl_xor_sync(0xFFFFFFFFu, bestj, off);
            if (ov > bestv || (ov == bestv && oj < bestj)) {
                bestv = ov; bestj = oj;
            }
        }
        if (lane == 0) g_posidx[sm_j[a]] = bestj;
    }
}

// A tile: 128 rows x 128B. B tile: 64 rows x 128B.
__device__ __forceinline__ void fill_a(uint32_t dst_sb, int row0, int tid) {
    const char* src = reinterpret_cast<const char*>(g_ebf);
#pragma unroll
    for (int k = 0; k < 4; k++) {
        int idx = tid + k * THREADS;
        int r = idx >> 3, c8 = idx & 7;
        CP16(dst_sb + r * ROWB + c8 * 16,
             src + (size_t)(row0 + r) * 128 + c8 * 16);
    }
}
__device__ __forceinline__ void fill_b(uint32_t dst_sb, int row0, int tid) {
    const char* src = reinterpret_cast<const char*>(g_ebf);
#pragma unroll
    for (int k = 0; k < 2; k++) {
        int idx = tid + k * THREADS;
        int r = idx >> 3, c8 = idx & 7;
        CP16(dst_sb + r * ROWB + c8 * 16,
             src + (size_t)(row0 + r) * 128 + c8 * 16);
    }
}

// ---------------------------------------------------------------- kernel 2: mining (R10 core + filter writeback)
__global__ __launch_bounds__(THREADS, 2)
void mine_kernel(const int* __restrict__ tgt) {
    extern __shared__ char smem[];
    const uint32_t sb = smem_u32(smem);
    const int tid = threadIdx.x, wid = tid >> 5, lane = tid & 31;
    const int wm = wid >> 1, wn = wid & 1;       // 4 x 2 warp grid
    const int m_warp = wm * 32, n_warp = wn * 32;
    const int strip = blockIdx.x, split = blockIdx.y;
    const int i0 = strip * BM;
    const int j0 = split * (N_ANCH / JSPLIT);

    float* s_sq = reinterpret_cast<float*>(smem + OFF_SQ);

    fill_a(sb + OFF_A, i0, tid);
    fill_b(sb + OFF_B, j0, tid);
    if (tid < BN) s_sq[tid] = g_sqb[j0 + tid];
    CP_COMMIT();
    fill_b(sb + OFF_B + BSTRIDE, j0 + BN, tid);
    if (tid < BN) s_sq[64 + tid] = g_sqb[j0 + BN + tid];
    CP_COMMIT();

    const float INF_F = __int_as_float(0x7f800000);
    float gm1[4], gm2[4];
#pragma unroll
    for (int s = 0; s < 4; s++) { gm1[s] = INF_F; gm2[s] = INF_F; }

    const uint32_t lmoff = (uint32_t)(lane & 15) * ROWB + ((lane & 16) ? 16 : 0);
    const uint32_t aA = sb + OFF_A + m_warp * ROWB + lmoff;

    CP_WAIT1();
    __syncthreads();
    uint32_t Af[2][KSTEPS][4];
#pragma unroll
    for (int mt = 0; mt < 2; mt++)
#pragma unroll
        for (int s = 0; s < KSTEPS; s++)
            LDSM_X4(Af[mt][s], aA + mt * (16 * ROWB) + s * 32);

    for (int t = 0; t < CHUNKS; t++) {
        const int buf = t % 3;
        if (t > 0) { CP_WAIT1(); __syncthreads(); }

        const uint32_t aB = sb + OFF_B + buf * BSTRIDE + n_warp * ROWB + lmoff;
        const float* sqv = s_sq + buf * 64;

        float d[2][4][4];
#pragma unroll
        for (int mt = 0; mt < 2; mt++)
#pragma unroll
            for (int nt = 0; nt < 4; nt++)
#pragma unroll
                for (int e = 0; e < 4; e++) d[mt][nt][e] = 0.f;

#pragma unroll
        for (int s = 0; s < KSTEPS; s++) {
            uint32_t Bf[2][4];
#pragma unroll
            for (int np = 0; np < 2; np++)
                LDSM_X4(Bf[np], aB + np * (16 * ROWB) + s * 32);
#pragma unroll
            for (int mt = 0; mt < 2; mt++)
#pragma unroll
                for (int nt = 0; nt < 4; nt++) {
                    int np = nt >> 1, sel = nt & 1;
                    MMA16816(d[mt][nt], Af[mt][s], Bf[np][sel], Bf[np][2 + sel]);
                }
        }

        if (t + 2 < CHUNKS) {
            const int nb = (t + 2) % 3;
            fill_b(sb + OFF_B + nb * BSTRIDE, j0 + (t + 2) * BN, tid);
            if (tid < BN) s_sq[nb * 64 + tid] = g_sqb[j0 + (t + 2) * BN + tid];
            CP_COMMIT();
        }

        const int jb10 = t * BN;
#pragma unroll
        for (int nt = 0; nt < 4; nt++)
#pragma unroll
            for (int c = 0; c < 2; c++) {
                int jl6 = n_warp + nt * 8 + (lane & 3) * 2 + c;
                unsigned jfield = (unsigned)(jb10 + jl6);
                float sqb = sqv[jl6];
#pragma unroll
                for (int mt = 0; mt < 2; mt++)
#pragma unroll
                    for (int h = 0; h < 2; h++) {
                        int sl = mt * 2 + h;
                        float key = fmaf(-2.0f, d[mt][nt][h * 2 + c], sqb);
                        float pk = __uint_as_float(
                            (__float_as_uint(key) & 0xFFFFFC00u) | jfield);
                        float sw = fmaxf(gm1[sl], pk);
                        gm1[sl] = fminf(gm1[sl], pk);
                        gm2[sl] = fminf(gm2[sl], sw);
                    }
            }
    }

    // Quad reduce
#pragma unroll
    for (int off = 1; off <= 2; off <<= 1) {
#pragma unroll
        for (int s = 0; s < 4; s++) {
            float o1 = __shfl_xor_sync(0xFFFFFFFFu, gm1[s], off);
            float o2 = __shfl_xor_sync(0xFFFFFFFFu, gm2[s], off);
            float n1 = fminf(gm1[s], o1);
            float n2 = fminf(fmaxf(gm1[s], o1), fminf(gm2[s], o2));
            gm1[s] = n1; gm2[s] = n2;
        }
    }

    // Cross-warp combine + class filter + writeback
    float2* s_sel = reinterpret_cast<float2*>(smem + OFF_B);
    __syncthreads();
    if ((lane & 3) == 0) {
#pragma unroll
        for (int mt = 0; mt < 2; mt++)
#pragma unroll
            for (int h = 0; h < 2; h++) {
                int sl = mt * 2 + h;
                int row = m_warp + mt * 16 + (lane >> 2) + h * 8;
                s_sel[wn * 128 + row] = make_float2(gm1[sl], gm2[sl]);
            }
    }
    __syncthreads();
    if (tid < 128) {
        float2 a = s_sel[tid];
        float2 b = s_sel[128 + tid];
        float n1 = fminf(a.x, b.x);
        float n2 = fminf(fmaxf(a.x, b.x), fminf(a.y, b.y));
        const int i = i0 + tid;
        const int mytgt = tgt[i];
        int j1 = j0 + (int)(__float_as_uint(n1) & 1023u);
        int j2 = j0 + (int)(__float_as_uint(n2) & 1023u);
        float bv; int bj;
        if (tgt[j1] != mytgt)      { bv = n1; bj = j1; }
        else if (tgt[j2] != mytgt) { bv = n2; bj = j2; }
        else                       { bv = INF_F; bj = 0x7FFFFFFF; }
        g_neg[split * N_ANCH + i] = make_float2(bv, __int_as_float(bj));
    }
}

// ---------------------------------------------------------------- kernel 3: loss + mean (4 threads/anchor, 128 CTAs)
__global__ void loss_kernel(const float* __restrict__ emb,
                            float* __restrict__ out) {
    __shared__ float red[128];
    __shared__ unsigned int s_win;
    const int tid = threadIdx.x;
    const int a = tid >> 2, sub = tid & 3;
    const int i = blockIdx.x * 64 + a;
    const float INF_F = __int_as_float(0x7f800000);

    // Each sub scans 2 splits of contiguous g_neg, quad shfl combines.
    float bv = INF_F; int bj = 0x7FFFFFFE;
#pragma unroll
    for (int k = 0; k < 2; k++) {
        float2 cnd = g_neg[(sub * 2 + k) * N_ANCH + i];
        int j = __float_as_int(cnd.y);
        if (cnd.x < bv || (cnd.x == bv && j < bj)) { bv = cnd.x; bj = j; }
    }
#pragma unroll
    for (int off = 1; off <= 2; off <<= 1) {
        float ov = __shfl_xor_sync(0xFFFFFFFFu, bv, off);
        int   oj = __shfl_xor_sync(0xFFFFFFFFu, bj, off);
        if (ov < bv || (ov == bv && oj < bj)) { bv = ov; bj = oj; }
    }
    const int n = min(bj, N_ANCH - 1);
    const int p = g_posidx[i];

    const float4* ei = reinterpret_cast<const float4*>(emb + (size_t)i * DIM) + sub * 4;
    const float4* ep = reinterpret_cast<const float4*>(emb + (size_t)p * DIM) + sub * 4;
    const float4* en = reinterpret_cast<const float4*>(emb + (size_t)n * DIM) + sub * 4;
    float ap = 0.f, an = 0.f;
#pragma unroll
    for (int k = 0; k < 4; k++) {
        float4 vi = ei[k], vp = ep[k], vn = en[k];
        float dx;
        dx = vi.x - vp.x; ap += dx * dx;
        dx = vi.y - vp.y; ap += dx * dx;
        dx = vi.z - vp.z; ap += dx * dx;
        dx = vi.w - vp.w; ap += dx * dx;
        dx = vi.x - vn.x; an += dx * dx;
        dx = vi.y - vn.y; an += dx * dx;
        dx = vi.z - vn.z; an += dx * dx;
        dx = vi.w - vn.w; an += dx * dx;
    }
    float v = ap - an;
    v += __shfl_xor_sync(0xFFFFFFFFu, v, 1);
    v += __shfl_xor_sync(0xFFFFFFFFu, v, 2);
    if (sub == 0) red[a] = fmaxf(v + MARGIN_F, 0.0f);
    __syncthreads();

#pragma unroll
    for (int off = 32; off > 0; off >>= 1) {
        if (tid < off) red[tid] += red[tid + off];
        __syncthreads();
    }
    if (tid == 0) {
        g_partial[blockIdx.x] = red[0];
        __threadfence();
        s_win = (atomicAdd(&g_count, 1u) == RBLOCKS - 1) ? 1u : 0u;
    }
    __syncthreads();
    if (!s_win) return;
    __threadfence();                 // acquire: see all partials

    // Parallel deterministic tail: fixed tree over 128 partials + resets
    if (tid < RBLOCKS) red[tid] = g_partial[tid];
    if (tid < NCLS) g_ccnt[tid] = 0;             // reset for replay
    __syncthreads();
#pragma unroll
    for (int off = 64; off > 0; off >>= 1) {
        if (tid < off) red[tid] += red[tid + off];
        __syncthreads();
    }
    if (tid == 0) { out[0] = red[0] / (float)N_ANCH; g_count = 0; }
}

// ----------------------------------------------------------------
extern "C" void kernel_launch(void* const* d_in, const int* in_sizes, int n_in,
                              void* d_out, int out_size) {
    const float* emb = (const float*)d_in[0];
    const int*   tgt = (const int*)d_in[1];
    float*       out = (float*)d_out;

    cudaFuncSetAttribute(mine_kernel, cudaFuncAttributeMaxDynamicSharedMemorySize,
                         SMEM_MINE);
    cudaFuncSetAttribute(pos_kernel, cudaFuncAttributeMaxDynamicSharedMemorySize,
                         SMEM_POS);

    prep_kernel<<<(N_ANCH * 4) / 256, 256>>>(emb, tgt);
    pos_kernel<<<NCLS * 4, THREADS, SMEM_POS>>>(emb);
    dim3 grid(STRIPS, JSPLIT);
    mine_kernel<<<grid, THREADS, SMEM_MINE>>>(tgt);
    loss_kernel<<<RBLOCKS, 256>>>(emb, out);
}